// round 11
// baseline (speedup 1.0000x reference)
#include <cuda_runtime.h>
#include <cuda_fp16.h>
#include <cstdint>

// ---------------- problem constants ----------------
#define KTOT   3072
#define NOUT   12288
#define MB     64             // batch (GEMM N side)
#define MTILE  32             // output rows per CTA
#define KC     64             // K per chunk
#define NCHUNK (KTOT / KC)    // 48
#define NTH    256
#define NCTA   (NOUT / MTILE) // 384

// ---- stage layout (4 stages) ----
// A codes : 32 rows x 256 B (int32, XOR-swizzled int2 positions) at +0
// B tile  : 64 rows x 128 B (fp16, SW128)                        at +8192
// scales  : 32 rows x float2                                      at +16384
#define SM_B      8192u
#define SM_S      16384u
#define ST_STRIDE 16640u
#define SM_BIAS   66560u      // 4*ST_STRIDE
#define SMEM_TOTAL 66816u
#define EPI_RSTRIDE 33        // floats per row in epilogue warp region

// x pre-converted to fp16 (k-major, [64][3072])
__device__ __align__(16) __half g_xh[MB * KTOT];

__global__ void xconv_kernel(const float* __restrict__ x) {
    int i = blockIdx.x * blockDim.x + threadIdx.x;   // indexes float4
    float4 v = ((const float4*)x)[i];
    __half2 h0 = __floats2half2_rn(v.x, v.y);
    __half2 h1 = __floats2half2_rn(v.z, v.w);
    uint2 r;
    r.x = *reinterpret_cast<uint32_t*>(&h0);
    r.y = *reinterpret_cast<uint32_t*>(&h1);
    ((uint2*)g_xh)[i] = r;
}

// ---------------- device helpers ----------------
__device__ __forceinline__ uint32_t smem_u32(const void* p) {
    uint32_t a;
    asm("{ .reg .u64 t; cvta.to.shared.u64 t, %1; cvt.u32.u64 %0, t; }" : "=r"(a) : "l"(p));
    return a;
}
__device__ __forceinline__ uint32_t swz(uint32_t off) {  // SW128 Swizzle<3,4,3>
    return off ^ ((off >> 3) & 0x70u);
}
__device__ __forceinline__ void cp_async16(uint32_t dst, const void* src) {
    asm volatile("cp.async.cg.shared.global [%0], [%1], 16;"
                 :: "r"(dst), "l"(src) : "memory");
}
__device__ __forceinline__ void cp_async8(uint32_t dst, const void* src) {
    asm volatile("cp.async.ca.shared.global [%0], [%1], 8;"
                 :: "r"(dst), "l"(src) : "memory");
}
#define CP_COMMIT()  asm volatile("cp.async.commit_group;" ::: "memory")
#define CP_WAIT(n)   asm volatile("cp.async.wait_group %0;" :: "n"(n) : "memory")

__device__ __forceinline__ void ldsm4(uint32_t* r, uint32_t addr) {
    asm volatile("ldmatrix.sync.aligned.m8n8.x4.shared.b16 {%0,%1,%2,%3}, [%4];"
                 : "=r"(r[0]), "=r"(r[1]), "=r"(r[2]), "=r"(r[3]) : "r"(addr));
}
__device__ __forceinline__ void lds64(uint32_t& x, uint32_t& y, uint32_t addr) {
    asm volatile("ld.shared.v2.b32 {%0,%1}, [%2];" : "=r"(x), "=r"(y) : "r"(addr));
}
__device__ __forceinline__ void mma16816(float* c,
                                         uint32_t a0, uint32_t a1, uint32_t a2, uint32_t a3,
                                         uint32_t b0, uint32_t b1) {
    asm volatile(
        "mma.sync.aligned.m16n8k16.row.col.f32.f16.f16.f32 "
        "{%0,%1,%2,%3}, {%4,%5,%6,%7}, {%8,%9}, {%0,%1,%2,%3};"
        : "+f"(c[0]), "+f"(c[1]), "+f"(c[2]), "+f"(c[3])
        : "r"(a0), "r"(a1), "r"(a2), "r"(a3), "r"(b0), "r"(b1));
}

__global__ __launch_bounds__(NTH, 3)
void dql_kernel(const int*   __restrict__ wq,
                const float* __restrict__ ws,
                const int*   __restrict__ bq,
                const float* __restrict__ bs,
                float*       __restrict__ out) {
    extern __shared__ __align__(16) char smem[];
    const uint32_t sb = smem_u32(smem);
    float* smf = (float*)smem;

    const int tid  = threadIdx.x;
    const int lane = tid & 31;
    const int wid  = tid >> 5;
    const int wk   = wid >> 1;     // k-split quarter (16 k per warp per chunk)
    const int wn   = wid & 1;      // batch half (32)
    const int cta  = blockIdx.x;

    // bias for this CTA's 32 output rows
    if (tid < MTILE) {
        const int o = cta * MTILE + tid;
        ((float*)(smem + SM_BIAS))[tid] = ((float)bq[o] - 128.0f) * bs[o >> 5];
    }

    // ---- cp.async producer mappings ----
    const int a_r   = tid >> 3;                 // 0..31 (weight row)
    const int a_seg = tid & 7;                  // 16B segment (covers a_seg, a_seg+8)
    const char* a_src0 = (const char*)(wq + (size_t)(cta * MTILE + a_r) * KTOT) + a_seg * 16;
    // XOR-swizzled int2 positions within the 256B code row
    const uint32_t a_e   = (uint32_t)((a_r & 7) << 2);
    const uint32_t a_d0  = (uint32_t)(a_r * 256) + (((uint32_t)(2 * a_seg)      ^ a_e) * 8);
    const uint32_t a_d1  = (uint32_t)(a_r * 256) + (((uint32_t)(2 * a_seg + 16) ^ a_e) * 8);
    const int brow  = tid >> 2;                 // 0..63 (batch row)
    const int bseg  = tid & 3;
    const char* b_src0 = (const char*)(g_xh + (size_t)brow * KTOT) + bseg * 16;
    const char* s_src0 = (const char*)(ws + (size_t)(cta * MTILE + tid) * (KTOT / 32));

    auto issueStage = [&](int c) {
        const uint32_t st = sb + (uint32_t)(c & 3) * ST_STRIDE;
        {   // A codes: 32 rows x 256B, swizzled placement
            const char* s = a_src0 + (size_t)c * 256;
            cp_async16(st + a_d0, s);
            cp_async16(st + a_d1, s + 128);
        }
        {   // B fp16 tile, SW128 swizzled
            const char* s = b_src0 + (size_t)c * (KC * 2);
            cp_async16(st + SM_B + swz((uint32_t)(brow * 128 + bseg * 16)), s);
            cp_async16(st + SM_B + swz((uint32_t)(brow * 128 + (bseg + 4) * 16)), s + 64);
        }
        if (tid < MTILE) {  // scales float2 per row
            cp_async8(st + SM_S + (uint32_t)(tid * 8), s_src0 + (size_t)c * 8);
        }
    };

    float acc[2][4][4];
#pragma unroll
    for (int mf = 0; mf < 2; mf++)
#pragma unroll
        for (int nf = 0; nf < 4; nf++)
#pragma unroll
            for (int i = 0; i < 4; i++) acc[mf][nf][i] = 0.0f;

    // ---- consumer addressing ----
    const int r      = lane >> 2;                  // fragment base row
    const int k2base = wk * 8 + (lane & 3);        // int2 index within 32
    const int kb4    = (wk >> 1) * 4;              // scale byte sel within float2
    const uint32_t b_lrow = (uint32_t)(wn * 32 + (lane & 7) + ((lane >> 4) & 1) * 8);
    const uint32_t b_lcol = (uint32_t)(((lane >> 3) & 1) * 16);
    const uint32_t kcol   = (uint32_t)(wk * 32);   // this warp's 16-k window (32B)
    const __half2 c1152 = __half2(__ushort_as_half((unsigned short)0x6480),
                                  __ushort_as_half((unsigned short)0x6480));

    // dequant stage (c&3) codes -> this warp's A fragments (registers)
    auto dqA = [&](int c, uint32_t a[2][4]) {
        const uint32_t As = sb + (uint32_t)(c & 3) * ST_STRIDE;
        const uint32_t Ss = As + SM_S;
#pragma unroll
        for (int j = 0; j < 4; j++) {
            const int R = r + 8 * j;
            float s;
            asm volatile("ld.shared.f32 %0, [%1];" : "=f"(s)
                         : "r"(Ss + (uint32_t)(R * 8 + kb4)));
            const __half2 s2 = __float2half2_rn(s);
            const uint32_t rowb = As + (uint32_t)(R * 256);
            const uint32_t e    = (uint32_t)((R & 7) << 2);
#pragma unroll
            for (int h = 0; h < 2; h++) {
                const uint32_t k2 = (uint32_t)(k2base + 4 * h);
                uint32_t cx, cy;
                lds64(cx, cy, rowb + ((k2 ^ e) * 8));
                uint32_t v = __byte_perm(cx, cy, 0x3430) | 0x64006400u;
                __half2 hv = __hmul2(__hsub2(*(__half2*)&v, c1152), s2);
                a[j >> 1][(j & 1) + 2 * h] = *(uint32_t*)&hv;
            }
        }
    };
    auto ldB = [&](int c, uint32_t b[2][4]) {
        const uint32_t Bs = sb + (uint32_t)(c & 3) * ST_STRIDE + SM_B;
#pragma unroll
        for (int nf2 = 0; nf2 < 2; nf2++)
            ldsm4(b[nf2], Bs + swz((b_lrow + (uint32_t)(nf2 * 16)) * 128 + kcol + b_lcol));
    };
    auto doMma = [&](uint32_t a[2][4], uint32_t b[2][4]) {
#pragma unroll
        for (int mf = 0; mf < 2; mf++)
#pragma unroll
            for (int nf = 0; nf < 4; nf++) {
                const int u = nf >> 1;
                const int p = (nf & 1) * 2;
                mma16816(acc[mf][nf], a[mf][0], a[mf][1], a[mf][2], a[mf][3],
                         b[u][p], b[u][p + 1]);
            }
    };

    // ---- prologue: stages 0,1 in flight ----
    issueStage(0); CP_COMMIT();
    issueStage(1); CP_COMMIT();

    // ---- main loop: 2 chunks per barrier, 4 stages ----
    // Order per iteration: wait(all pending = cc, cc+1) -> barrier ->
    // issue cc+2, cc+3 (slots free: their last readers finished before the
    // barrier) -> compute cc, cc+1. Loads for cc+2/3 overlap both computes.
    for (int cc = 0; cc < NCHUNK; cc += 2) {
        CP_WAIT(0);                  // stages cc, cc+1 complete
        __syncthreads();             // visibility + slot-reuse safety

        if (cc + 2 < NCHUNK) { issueStage(cc + 2); CP_COMMIT(); }
        if (cc + 3 < NCHUNK) { issueStage(cc + 3); CP_COMMIT(); }

        uint32_t a0[2][4], b0[2][4], a1[2][4], b1[2][4];
        dqA(cc, a0);
        ldB(cc, b0);
        dqA(cc + 1, a1);
        ldB(cc + 1, b1);
        doMma(a0, b0);
        doMma(a1, b1);
    }

    // ---- epilogue: per-warp partials -> smem, reduce over wk, bias, store ----
    __syncthreads();
    {
        const uint32_t wbase = (uint32_t)(wid * 32 * EPI_RSTRIDE);
        const int g = lane >> 2;
        const int q = (lane & 3) * 2;
#pragma unroll
        for (int mf = 0; mf < 2; mf++)
#pragma unroll
            for (int nf = 0; nf < 4; nf++) {
                const int row = mf * 16 + g;
                const int col = nf * 8 + q;
                smf[wbase + row * EPI_RSTRIDE + col]            = acc[mf][nf][0];
                smf[wbase + row * EPI_RSTRIDE + col + 1]        = acc[mf][nf][1];
                smf[wbase + (row + 8) * EPI_RSTRIDE + col]      = acc[mf][nf][2];
                smf[wbase + (row + 8) * EPI_RSTRIDE + col + 1]  = acc[mf][nf][3];
            }
    }
    __syncthreads();
    {
        const int row = tid & 31;
        const int mg  = tid >> 5;
        const float bias = ((const float*)(smem + SM_BIAS))[row];
        float* op = out + (size_t)cta * MTILE + row;
#pragma unroll
        for (int j = 0; j < 8; j++) {
            const int m  = mg * 8 + j;
            const int wn_ = m >> 5;
            const int ml  = m & 31;
            float v = bias;
#pragma unroll
            for (int k4 = 0; k4 < 4; k4++)
                v += smf[(uint32_t)((k4 * 2 + wn_) * 32 * EPI_RSTRIDE + row * EPI_RSTRIDE + ml)];
            op[(size_t)m * NOUT] = v;
        }
    }
}

extern "C" void kernel_launch(void* const* d_in, const int* in_sizes, int n_in,
                              void* d_out, int out_size) {
    (void)in_sizes; (void)n_in; (void)out_size;
    xconv_kernel<<<(MB * KTOT / 4) / NTH, NTH>>>((const float*)d_in[0]);
    cudaFuncSetAttribute(dql_kernel, cudaFuncAttributeMaxDynamicSharedMemorySize, SMEM_TOTAL);
    dql_kernel<<<NCTA, NTH, SMEM_TOTAL>>>(
        (const int*)d_in[1],     // w_q
        (const float*)d_in[2],   // w_scales
        (const int*)d_in[3],     // b_q
        (const float*)d_in[4],   // b_scales
        (float*)d_out);
}